// round 3
// baseline (speedup 1.0000x reference)
#include <cuda_runtime.h>
#include <math.h>

// Problem constants
#define BB   4
#define CC   256
#define CQKd 32
#define NN   4096

// ---------------- scratch (static __device__, no allocations) ----------------
__device__ float g_q [(size_t)BB * NN * CQKd];   // [b][m][32]
__device__ float g_k [(size_t)BB * CQKd * NN];   // [b][c][n]
__device__ float g_v [(size_t)BB * CC * NN];     // [b][co][n]
__device__ float g_vT[(size_t)BB * NN * CC];     // [b][n][co]
__device__ float g_e [(size_t)BB * NN * NN];     // [b][m][n]  (256 MB)
__device__ float g_o [(size_t)BB * NN * CC];     // [b][m][co]
__device__ float g_oT[(size_t)BB * CC * NN];     // [b][co][m]

// ---------------- fused q/k projection ----------------
// q[b][m][c] = sum_C Wq[c][C] x[b][C][m] + bq[c]   (c-minor, m-major)
// k[b][c][n] = sum_C Wk[c][C] x[b][C][n] + bk[c]   (n-minor, c-major)
__global__ void qk_proj_kernel(const float* __restrict__ x,
                               const float* __restrict__ Wq, const float* __restrict__ bq,
                               const float* __restrict__ Wk, const float* __restrict__ bk,
                               float* __restrict__ q, float* __restrict__ ko)
{
    const int b  = blockIdx.z;
    const int m0 = blockIdx.x * 128;
    const float* xb = x + (size_t)b * CC * NN;

    __shared__ float sx[32][128];   // [C-chunk][m]
    __shared__ float sw[64][32];    // [co (q:0..31, k:32..63)][C-chunk]
    __shared__ float sq[128 * 32];  // staging for coalesced q writes

    const int t    = threadIdx.x;       // 256 threads
    const int mi   = t & 127;
    const int half = t >> 7;            // 0 -> q, 1 -> k

    float acc[32];
    const float* bias = half ? bk : bq;
#pragma unroll
    for (int j = 0; j < 32; j++) acc[j] = bias[j];

    for (int c0 = 0; c0 < CC; c0 += 32) {
#pragma unroll
        for (int i = 0; i < 16; i++) {
            int idx = t + i * 256;
            int r = idx >> 7, mm = idx & 127;
            sx[r][mm] = xb[(size_t)(c0 + r) * NN + m0 + mm];
        }
#pragma unroll
        for (int i = 0; i < 8; i++) {
            int idx = t + i * 256;
            int co = idx >> 5, cc = idx & 31;
            sw[co][cc] = (co < 32) ? Wq[co * 256 + c0 + cc]
                                   : Wk[(co - 32) * 256 + c0 + cc];
        }
        __syncthreads();
#pragma unroll
        for (int cc = 0; cc < 32; cc++) {
            float xv = sx[cc][mi];
#pragma unroll
            for (int j = 0; j < 32; j++) acc[j] += sw[half * 32 + j][cc] * xv;
        }
        __syncthreads();
    }

    if (half == 0) {
#pragma unroll
        for (int j = 0; j < 32; j++) sq[mi * 32 + j] = acc[j];
    } else {
        float* kb = ko + (size_t)b * CQKd * NN;
#pragma unroll
        for (int j = 0; j < 32; j++) kb[(size_t)j * NN + m0 + mi] = acc[j];
    }
    __syncthreads();
    float* qb = q + (size_t)b * NN * CQKd + (size_t)m0 * CQKd;
#pragma unroll
    for (int i = 0; i < 16; i++) qb[t + i * 256] = sq[t + i * 256];
}

// ---------------- generic fp32 SGEMM: 128x128 tile, BK=8, 8x8 micro ----------------
// C[i][j] = sum_k A[i][k] * Bsrc[k][j] (+ bias[i])
// Bsrc = B1 rows for k < ksplit, else B2 rows (k - ksplit).
// All of M, N multiples of 128; K multiple of 8. grid: (N/128, M/128, batch)
__global__ void sgemm128(const float* __restrict__ A, int lda, size_t sAb,
                         const float* __restrict__ B1, int ldb1, size_t sB1b,
                         const float* __restrict__ B2, int ldb2, size_t sB2b, int ksplit,
                         float* __restrict__ C, int ldc, size_t sCb,
                         const float* __restrict__ bias, int K)
{
    const int b = blockIdx.z;
    A  += (size_t)b * sAb;
    B1 += (size_t)b * sB1b;
    if (B2) B2 += (size_t)b * sB2b;
    C  += (size_t)b * sCb;

    const int m0 = blockIdx.y * 128;
    const int n0 = blockIdx.x * 128;

    __shared__ float sA[8][128];   // [k][m]
    __shared__ float sB[8][128];   // [k][n]

    const int t  = threadIdx.x;     // 256
    const int tx = t & 15;
    const int ty = t >> 4;

    const int ar = t >> 1;          // A tile row    0..127
    const int ak = (t & 1) * 4;     // A tile k      0 or 4
    const int bk = t >> 5;          // B tile k      0..7
    const int bn = (t & 31) * 4;    // B tile col

    float acc[8][8];
#pragma unroll
    for (int i = 0; i < 8; i++)
#pragma unroll
        for (int j = 0; j < 8; j++) acc[i][j] = 0.f;

    for (int k0 = 0; k0 < K; k0 += 8) {
        float4 av = *(const float4*)&A[(size_t)(m0 + ar) * lda + k0 + ak];
        const float* Bp;
        int ldb;
        if (k0 < ksplit) { Bp = B1 + (size_t)k0 * ldb1;            ldb = ldb1; }
        else             { Bp = B2 + (size_t)(k0 - ksplit) * ldb2; ldb = ldb2; }
        float4 bv = *(const float4*)&Bp[(size_t)bk * ldb + n0 + bn];

        sA[ak + 0][ar] = av.x;
        sA[ak + 1][ar] = av.y;
        sA[ak + 2][ar] = av.z;
        sA[ak + 3][ar] = av.w;
        *(float4*)&sB[bk][bn] = bv;
        __syncthreads();

#pragma unroll
        for (int kk = 0; kk < 8; kk++) {
            float4 a0 = *(const float4*)&sA[kk][ty * 8];
            float4 a1 = *(const float4*)&sA[kk][ty * 8 + 4];
            float4 b0 = *(const float4*)&sB[kk][tx * 8];
            float4 b1 = *(const float4*)&sB[kk][tx * 8 + 4];
            float a[8] = {a0.x, a0.y, a0.z, a0.w, a1.x, a1.y, a1.z, a1.w};
            float bb[8] = {b0.x, b0.y, b0.z, b0.w, b1.x, b1.y, b1.z, b1.w};
#pragma unroll
            for (int i = 0; i < 8; i++)
#pragma unroll
                for (int j = 0; j < 8; j++) acc[i][j] += a[i] * bb[j];
        }
        __syncthreads();
    }

#pragma unroll
    for (int i = 0; i < 8; i++) {
        int m = m0 + ty * 8 + i;
        float bi = bias ? bias[m] : 0.f;
        float4 o0, o1;
        o0.x = acc[i][0] + bi; o0.y = acc[i][1] + bi;
        o0.z = acc[i][2] + bi; o0.w = acc[i][3] + bi;
        o1.x = acc[i][4] + bi; o1.y = acc[i][5] + bi;
        o1.z = acc[i][6] + bi; o1.w = acc[i][7] + bi;
        *(float4*)&C[(size_t)m * ldc + n0 + tx * 8]     = o0;
        *(float4*)&C[(size_t)m * ldc + n0 + tx * 8 + 4] = o1;
    }
}

// ---------------- row softmax over 4096 elements ----------------
__global__ void softmax4096(float* __restrict__ e)
{
    float4* p4 = (float4*)(e + (size_t)blockIdx.x * NN);
    const int t = threadIdx.x;   // 256

    float4 v[4];
    float mx = -3.4e38f;
#pragma unroll
    for (int i = 0; i < 4; i++) {
        v[i] = p4[t + i * 256];
        mx = fmaxf(mx, fmaxf(fmaxf(v[i].x, v[i].y), fmaxf(v[i].z, v[i].w)));
    }
    __shared__ float smx[8];
    __shared__ float ssm[8];
#pragma unroll
    for (int o = 16; o; o >>= 1) mx = fmaxf(mx, __shfl_xor_sync(0xffffffffu, mx, o));
    if ((t & 31) == 0) smx[t >> 5] = mx;
    __syncthreads();
    mx = smx[0];
#pragma unroll
    for (int i = 1; i < 8; i++) mx = fmaxf(mx, smx[i]);

    float s = 0.f;
#pragma unroll
    for (int i = 0; i < 4; i++) {
        v[i].x = __expf(v[i].x - mx);
        v[i].y = __expf(v[i].y - mx);
        v[i].z = __expf(v[i].z - mx);
        v[i].w = __expf(v[i].w - mx);
        s += v[i].x + v[i].y + v[i].z + v[i].w;
    }
#pragma unroll
    for (int o = 16; o; o >>= 1) s += __shfl_xor_sync(0xffffffffu, s, o);
    if ((t & 31) == 0) ssm[t >> 5] = s;
    __syncthreads();
    s = 0.f;
#pragma unroll
    for (int i = 0; i < 8; i++) s += ssm[i];
    float inv = 1.f / s;
#pragma unroll
    for (int i = 0; i < 4; i++) {
        v[i].x *= inv; v[i].y *= inv; v[i].z *= inv; v[i].w *= inv;
        p4[t + i * 256] = v[i];
    }
}

// ---------------- 32x32 tiled transpose: dst[c][r] = src[r][c] ----------------
__global__ void transpose_kernel(const float* __restrict__ src, float* __restrict__ dst,
                                 int R, int Cn, size_t sSb, size_t sDb)
{
    __shared__ float tile[32][33];
    const int b = blockIdx.z;
    src += (size_t)b * sSb;
    dst += (size_t)b * sDb;
    const int c0 = blockIdx.x * 32;
    const int r0 = blockIdx.y * 32;
    const int tx = threadIdx.x, ty = threadIdx.y;  // (32, 8)
#pragma unroll
    for (int i = 0; i < 32; i += 8)
        tile[ty + i][tx] = src[(size_t)(r0 + ty + i) * Cn + c0 + tx];
    __syncthreads();
#pragma unroll
    for (int i = 0; i < 32; i += 8)
        dst[(size_t)(c0 + ty + i) * R + r0 + tx] = tile[tx][ty + i];
}

// ---------------- launch ----------------
extern "C" void kernel_launch(void* const* d_in, const int* in_sizes, int n_in,
                              void* d_out, int out_size)
{
    const float* x  = (const float*)d_in[0];
    const float* Wq = (const float*)d_in[1];
    const float* bq = (const float*)d_in[2];
    const float* Wk = (const float*)d_in[3];
    const float* bk = (const float*)d_in[4];
    const float* Wv = (const float*)d_in[5];
    const float* bv = (const float*)d_in[6];
    const float* Wo = (const float*)d_in[7];
    const float* bo = (const float*)d_in[8];
    float* y = (float*)d_out;

    float *p_q, *p_k, *p_v, *p_vT, *p_e, *p_o, *p_oT;
    cudaGetSymbolAddress((void**)&p_q,  g_q);
    cudaGetSymbolAddress((void**)&p_k,  g_k);
    cudaGetSymbolAddress((void**)&p_v,  g_v);
    cudaGetSymbolAddress((void**)&p_vT, g_vT);
    cudaGetSymbolAddress((void**)&p_e,  g_e);
    cudaGetSymbolAddress((void**)&p_o,  g_o);
    cudaGetSymbolAddress((void**)&p_oT, g_oT);

    const size_t sX = (size_t)CC * NN;     // per-batch stride of x / v / oT / y
    const size_t sE = (size_t)NN * NN;

    // 1. q/k projection
    qk_proj_kernel<<<dim3(NN / 128, 1, BB), 256>>>(x, Wq, bq, Wk, bk, p_q, p_k);

    // 2. v = Wv @ x + bv   -> g_v [b][co][n]
    sgemm128<<<dim3(NN / 128, CC / 128, BB), 256>>>(
        Wv, CC, 0,
        x, NN, sX,
        nullptr, 0, 0, CC,
        p_v, NN, sX,
        bv, CC);

    // 3. transpose v -> vT [b][n][co]
    transpose_kernel<<<dim3(NN / 32, CC / 32, BB), dim3(32, 8)>>>(
        p_v, p_vT, CC, NN, sX, sX);

    // 4. energy = q @ k   -> g_e [b][m][n]
    sgemm128<<<dim3(NN / 128, NN / 128, BB), 256>>>(
        p_q, CQKd, (size_t)NN * CQKd,
        p_k, NN, (size_t)CQKd * NN,
        nullptr, 0, 0, CQKd,
        p_e, NN, sE,
        nullptr, CQKd);

    // 5. softmax rows
    softmax4096<<<BB * NN, 256>>>(p_e);

    // 6. o = attn @ vT  -> g_o [b][m][co]
    sgemm128<<<dim3(CC / 128, NN / 128, BB), 256>>>(
        p_e, NN, sE,
        p_vT, CC, (size_t)NN * CC,
        nullptr, 0, 0, NN,
        p_o, CC, (size_t)NN * CC,
        nullptr, NN);

    // 7. transpose o -> oT [b][co][m]
    transpose_kernel<<<dim3(CC / 32, NN / 32, BB), dim3(32, 8)>>>(
        p_o, p_oT, NN, CC, (size_t)NN * CC, sX);

    // 8. y = Wo @ concat(oT, x) + bo
    sgemm128<<<dim3(NN / 128, CC / 128, BB), 256>>>(
        Wo, 2 * CC, 0,
        p_oT, NN, sX,
        x, NN, sX, CC,
        y, NN, sX,
        bo, 2 * CC);
}

// round 6
// speedup vs baseline: 3.1580x; 3.1580x over previous
#include <cuda_runtime.h>
#include <cstdint>
#include <math.h>

// Problem constants
#define BB   4
#define CC   256
#define CQK  32
#define NNp  4096

// ---------------- scratch ----------------
__device__ float g_q [(size_t)BB * NNp * CQK];   // [b][m][32]   K-major, tf32-rounded
__device__ float g_k [(size_t)BB * NNp * CQK];   // [b][n][32]   K-major, tf32-rounded
__device__ float g_v [(size_t)BB * CC * NNp];    // [b][co][n]   tf32-rounded
__device__ float g_e [(size_t)BB * NNp * NNp];   // [b][m][n]    (256 MB)
__device__ float g_o [(size_t)BB * NNp * CC];    // [b][m][co]   tf32-rounded
__device__ float g_xT[(size_t)BB * NNp * CC];    // [b][m][c]    tf32-rounded
__device__ float g_wv[(size_t)CC * CC];          // rounded Wv
__device__ float g_wo[(size_t)CC * 2 * CC];      // rounded Wo

// ---------------- helpers ----------------
__device__ __forceinline__ float tf32r(float x) {
    uint32_t y;
    asm("cvt.rna.tf32.f32 %0, %1;" : "=r"(y) : "f"(x));   // tf32 dst is .b32
    return __uint_as_float(y);
}

__device__ __forceinline__ uint32_t smem_u32(const void* p) {
    uint32_t a;
    asm("{ .reg .u64 t; cvta.to.shared.u64 t, %1; cvt.u32.u64 %0, t; }"
        : "=r"(a) : "l"(p));
    return a;
}

#define CP_ASYNC16(dst, src) \
    asm volatile("cp.async.cg.shared.global [%0], [%1], 16;" :: "r"(dst), "l"(src))
#define CP_COMMIT() asm volatile("cp.async.commit_group;" ::: "memory")
#define CP_WAIT(n)  asm volatile("cp.async.wait_group %0;" :: "n"(n) : "memory")

__device__ __forceinline__ void mma_tf32(float* d, const uint32_t* a, const uint32_t* b) {
    asm volatile(
        "mma.sync.aligned.m16n8k8.row.col.f32.tf32.tf32.f32 "
        "{%0,%1,%2,%3}, {%4,%5,%6,%7}, {%8,%9}, {%0,%1,%2,%3};"
        : "+f"(d[0]), "+f"(d[1]), "+f"(d[2]), "+f"(d[3])
        : "r"(a[0]), "r"(a[1]), "r"(a[2]), "r"(a[3]), "r"(b[0]), "r"(b[1]));
}

// ---------------- tf32 mma.sync GEMM ----------------
// D[M,N] = A[M,K] * B[N,K]^T (+ bias[m]), optional tf32-round of output.
// Tile 128x128, BK=32, 256 threads = 8 warps (4 along M x 2 along N), warp 32x64.
// B rows: B1 for k < ksplit, else B2 at (k - ksplit).
// Inputs must be pre-rounded to tf32 for exact mma semantics.
#define SROW 36                 // padded row stride in floats
#define TILE_F (128 * SROW)     // floats per operand tile

__global__ void __launch_bounds__(256, 2) tc_gemm(
    const float* __restrict__ A, int lda, size_t sAb,
    const float* __restrict__ B1, int ldb1, size_t sB1b,
    const float* __restrict__ B2, int ldb2, size_t sB2b, int ksplit,
    float* __restrict__ C, int ldc, size_t sCb,
    const float* __restrict__ bias, int K, int round_out)
{
    extern __shared__ float4 smem4[];
    float* sm = (float*)smem4;   // [2 buffers][A tile | B tile]

    const int b = blockIdx.z;
    A  += (size_t)b * sAb;
    B1 += (size_t)b * sB1b;
    const float* B2p = B2 ? (B2 + (size_t)b * sB2b) : nullptr;
    C  += (size_t)b * sCb;

    const int n0 = blockIdx.x * 128;
    const int m0 = blockIdx.y * 128;
    const int t    = threadIdx.x;
    const int lane = t & 31;
    const int warp = t >> 5;
    const int wm = (warp & 3) * 32;   // warp offset along M
    const int wn = (warp >> 2) * 64;  // warp offset along N
    const int gr = lane >> 2;         // group row 0..7
    const int gc = lane & 3;          // group col 0..3

    const uint32_t sbase = smem_u32(sm);
    const int ldr = t >> 3;           // loader row 0..31 step (r = t/8 + i*32)
    const int ldc4 = (t & 7) * 4;     // loader col (floats)

    const int nk = K / 32;

    auto issue_tile = [&](int kb, int buf) {
        const int k0 = kb * 32;
        // A tile: 128 x 32 floats, 4 chunks of 16B per thread
        {
            const float* src = A + (size_t)(m0 + ldr) * lda + k0 + ldc4;
            uint32_t dst = sbase + (uint32_t)(buf * 2 * TILE_F) * 4u
                         + (uint32_t)(ldr * SROW + ldc4) * 4u;
#pragma unroll
            for (int i = 0; i < 4; i++) {
                CP_ASYNC16(dst + (uint32_t)(i * 32 * SROW) * 4u,
                           src + (size_t)(i * 32) * lda);
            }
        }
        // B tile: two-source
        {
            const float* Bp; int ldb, kk;
            if (k0 < ksplit) { Bp = B1;  ldb = ldb1; kk = k0; }
            else             { Bp = B2p; ldb = ldb2; kk = k0 - ksplit; }
            const float* src = Bp + (size_t)(n0 + ldr) * ldb + kk + ldc4;
            uint32_t dst = sbase + (uint32_t)((buf * 2 + 1) * TILE_F) * 4u
                         + (uint32_t)(ldr * SROW + ldc4) * 4u;
#pragma unroll
            for (int i = 0; i < 4; i++) {
                CP_ASYNC16(dst + (uint32_t)(i * 32 * SROW) * 4u,
                           src + (size_t)(i * 32) * ldb);
            }
        }
        CP_COMMIT();
    };

    float acc[2][8][4];
#pragma unroll
    for (int mf = 0; mf < 2; mf++)
#pragma unroll
        for (int nf = 0; nf < 8; nf++)
#pragma unroll
            for (int j = 0; j < 4; j++) acc[mf][nf][j] = 0.f;

    issue_tile(0, 0);

    for (int kb = 0; kb < nk; kb++) {
        const int buf = kb & 1;
        if (kb + 1 < nk) {
            issue_tile(kb + 1, buf ^ 1);
            CP_WAIT(1);
        } else {
            CP_WAIT(0);
        }
        __syncthreads();

        const float* sA = sm + buf * 2 * TILE_F;
        const float* sB = sA + TILE_F;
#pragma unroll
        for (int ks = 0; ks < 4; ks++) {
            const int k0 = ks * 8;
            uint32_t afr[2][4], bfr[8][2];
#pragma unroll
            for (int mf = 0; mf < 2; mf++) {
                const float* p = sA + (wm + mf * 16 + gr) * SROW + k0 + gc;
                afr[mf][0] = __float_as_uint(p[0]);
                afr[mf][1] = __float_as_uint(p[8 * SROW]);
                afr[mf][2] = __float_as_uint(p[4]);
                afr[mf][3] = __float_as_uint(p[8 * SROW + 4]);
            }
#pragma unroll
            for (int nf = 0; nf < 8; nf++) {
                const float* p = sB + (wn + nf * 8 + gr) * SROW + k0 + gc;
                bfr[nf][0] = __float_as_uint(p[0]);
                bfr[nf][1] = __float_as_uint(p[4]);
            }
#pragma unroll
            for (int mf = 0; mf < 2; mf++)
#pragma unroll
                for (int nf = 0; nf < 8; nf++)
                    mma_tf32(acc[mf][nf], afr[mf], bfr[nf]);
        }
        __syncthreads();
    }

    // ---- epilogue ----
#pragma unroll
    for (int mf = 0; mf < 2; mf++) {
        const int m = m0 + wm + mf * 16 + gr;
        const float bi0 = bias ? bias[m]     : 0.f;
        const float bi1 = bias ? bias[m + 8] : 0.f;
#pragma unroll
        for (int nf = 0; nf < 8; nf++) {
            const int n = n0 + wn + nf * 8 + gc * 2;
            float2 r0, r1;
            r0.x = acc[mf][nf][0] + bi0; r0.y = acc[mf][nf][1] + bi0;
            r1.x = acc[mf][nf][2] + bi1; r1.y = acc[mf][nf][3] + bi1;
            if (round_out) {
                r0.x = tf32r(r0.x); r0.y = tf32r(r0.y);
                r1.x = tf32r(r1.x); r1.y = tf32r(r1.y);
            }
            *(float2*)&C[(size_t)m * ldc + n]       = r0;
            *(float2*)&C[(size_t)(m + 8) * ldc + n] = r1;
        }
    }
}

// ---------------- weight rounding prep ----------------
__global__ void round_weights(const float* __restrict__ Wv, const float* __restrict__ Wo,
                              float* __restrict__ wv_r, float* __restrict__ wo_r)
{
    int i = blockIdx.x * 256 + threadIdx.x;
    if (i < CC * CC)     wv_r[i] = tf32r(Wv[i]);
    if (i < CC * 2 * CC) wo_r[i] = tf32r(Wo[i]);
}

// ---------------- fused q/k projection -> [b][n][32] K-major, tf32-rounded ----
__global__ void qk_proj_kernel(const float* __restrict__ x,
                               const float* __restrict__ Wq, const float* __restrict__ bq,
                               const float* __restrict__ Wk, const float* __restrict__ bk,
                               float* __restrict__ q, float* __restrict__ ko)
{
    const int b  = blockIdx.z;
    const int m0 = blockIdx.x * 128;
    const float* xb = x + (size_t)b * CC * NNp;

    __shared__ float sx[32][128];
    __shared__ float sw[64][32];

    const int t    = threadIdx.x;       // 256
    const int mi   = t & 127;
    const int half = t >> 7;            // 0 -> q, 1 -> k

    float acc[32];
    const float* bias = half ? bk : bq;
#pragma unroll
    for (int j = 0; j < 32; j++) acc[j] = bias[j];

    for (int c0 = 0; c0 < CC; c0 += 32) {
#pragma unroll
        for (int i = 0; i < 16; i++) {
            int idx = t + i * 256;
            int r = idx >> 7, mm = idx & 127;
            sx[r][mm] = xb[(size_t)(c0 + r) * NNp + m0 + mm];
        }
#pragma unroll
        for (int i = 0; i < 8; i++) {
            int idx = t + i * 256;
            int co = idx >> 5, cc = idx & 31;
            sw[co][cc] = (co < 32) ? Wq[co * 256 + c0 + cc]
                                   : Wk[(co - 32) * 256 + c0 + cc];
        }
        __syncthreads();
#pragma unroll
        for (int cc = 0; cc < 32; cc++) {
            float xv = sx[cc][mi];
#pragma unroll
            for (int j = 0; j < 32; j++) acc[j] += sw[half * 32 + j][cc] * xv;
        }
        __syncthreads();
    }

    float* dst = (half ? ko : q) + (size_t)b * NNp * CQK + (size_t)(m0 + mi) * CQK;
#pragma unroll
    for (int j = 0; j < 32; j += 4)
        *(float4*)&dst[j] = make_float4(tf32r(acc[j]), tf32r(acc[j + 1]),
                                        tf32r(acc[j + 2]), tf32r(acc[j + 3]));
}

// ---------------- row softmax over 4096, tf32-rounded output ----------------
__global__ void softmax4096(float* __restrict__ e)
{
    float4* p4 = (float4*)(e + (size_t)blockIdx.x * NNp);
    const int t = threadIdx.x;   // 256

    float4 v[4];
    float mx = -3.4e38f;
#pragma unroll
    for (int i = 0; i < 4; i++) {
        v[i] = p4[t + i * 256];
        mx = fmaxf(mx, fmaxf(fmaxf(v[i].x, v[i].y), fmaxf(v[i].z, v[i].w)));
    }
    __shared__ float smx[8];
    __shared__ float ssm[8];
#pragma unroll
    for (int o = 16; o; o >>= 1) mx = fmaxf(mx, __shfl_xor_sync(0xffffffffu, mx, o));
    if ((t & 31) == 0) smx[t >> 5] = mx;
    __syncthreads();
    mx = smx[0];
#pragma unroll
    for (int i = 1; i < 8; i++) mx = fmaxf(mx, smx[i]);

    float s = 0.f;
#pragma unroll
    for (int i = 0; i < 4; i++) {
        v[i].x = __expf(v[i].x - mx);
        v[i].y = __expf(v[i].y - mx);
        v[i].z = __expf(v[i].z - mx);
        v[i].w = __expf(v[i].w - mx);
        s += v[i].x + v[i].y + v[i].z + v[i].w;
    }
#pragma unroll
    for (int o = 16; o; o >>= 1) s += __shfl_xor_sync(0xffffffffu, s, o);
    if ((t & 31) == 0) ssm[t >> 5] = s;
    __syncthreads();
    s = 0.f;
#pragma unroll
    for (int i = 0; i < 8; i++) s += ssm[i];
    float inv = 1.f / s;
#pragma unroll
    for (int i = 0; i < 4; i++) {
        v[i].x = tf32r(v[i].x * inv); v[i].y = tf32r(v[i].y * inv);
        v[i].z = tf32r(v[i].z * inv); v[i].w = tf32r(v[i].w * inv);
        p4[t + i * 256] = v[i];
    }
}

// ---------------- 32x32 transpose with tf32 rounding ----------------
__global__ void transpose_kernel(const float* __restrict__ src, float* __restrict__ dst,
                                 int R, int Cn, size_t sSb, size_t sDb)
{
    __shared__ float tile[32][33];
    const int b = blockIdx.z;
    src += (size_t)b * sSb;
    dst += (size_t)b * sDb;
    const int c0 = blockIdx.x * 32;
    const int r0 = blockIdx.y * 32;
    const int tx = threadIdx.x, ty = threadIdx.y;  // (32, 8)
#pragma unroll
    for (int i = 0; i < 32; i += 8)
        tile[ty + i][tx] = tf32r(src[(size_t)(r0 + ty + i) * Cn + c0 + tx]);
    __syncthreads();
#pragma unroll
    for (int i = 0; i < 32; i += 8)
        dst[(size_t)(c0 + ty + i) * R + r0 + tx] = tile[tx][ty + i];
}

// ---------------- launch ----------------
extern "C" void kernel_launch(void* const* d_in, const int* in_sizes, int n_in,
                              void* d_out, int out_size)
{
    const float* x  = (const float*)d_in[0];
    const float* Wq = (const float*)d_in[1];
    const float* bq = (const float*)d_in[2];
    const float* Wk = (const float*)d_in[3];
    const float* bk = (const float*)d_in[4];
    const float* Wv = (const float*)d_in[5];
    const float* bv = (const float*)d_in[6];
    const float* Wo = (const float*)d_in[7];
    const float* bo = (const float*)d_in[8];
    float* y = (float*)d_out;

    float *p_q, *p_k, *p_v, *p_e, *p_o, *p_xT, *p_wv, *p_wo;
    cudaGetSymbolAddress((void**)&p_q,  g_q);
    cudaGetSymbolAddress((void**)&p_k,  g_k);
    cudaGetSymbolAddress((void**)&p_v,  g_v);
    cudaGetSymbolAddress((void**)&p_e,  g_e);
    cudaGetSymbolAddress((void**)&p_o,  g_o);
    cudaGetSymbolAddress((void**)&p_xT, g_xT);
    cudaGetSymbolAddress((void**)&p_wv, g_wv);
    cudaGetSymbolAddress((void**)&p_wo, g_wo);

    const size_t sX = (size_t)CC * NNp;
    const size_t sQ = (size_t)NNp * CQK;
    const size_t sE = (size_t)NNp * NNp;

    const int SMEM = 4 * TILE_F * 4;   // 2 buffers x (A+B) tiles = 73728 B
    cudaFuncSetAttribute(tc_gemm, cudaFuncAttributeMaxDynamicSharedMemorySize, SMEM);

    // 0. round weights to tf32
    round_weights<<<(CC * 2 * CC + 255) / 256, 256>>>(Wv, Wo, p_wv, p_wo);

    // 1. xT[b][m][c] = tf32(x[b][c][m])
    transpose_kernel<<<dim3(NNp / 32, CC / 32, BB), dim3(32, 8)>>>(
        x, p_xT, CC, NNp, sX, sX);

    // 2. q/k projection
    qk_proj_kernel<<<dim3(NNp / 128, 1, BB), 256>>>(x, Wq, bq, Wk, bk, p_q, p_k);

    // 3. v[co][n] = Wv @ x + bv : M=256, N=4096, K=256
    tc_gemm<<<dim3(NNp / 128, CC / 128, BB), 256, SMEM>>>(
        p_wv, CC, 0,
        p_xT, CC, sX,
        nullptr, 0, 0, CC,
        p_v, NNp, sX,
        bv, CC, 1);

    // 4. energy[m][n] = q @ k^T : M=4096, N=4096, K=32
    tc_gemm<<<dim3(NNp / 128, NNp / 128, BB), 256, SMEM>>>(
        p_q, CQK, sQ,
        p_k, CQK, sQ,
        nullptr, 0, 0, CQK,
        p_e, NNp, sE,
        nullptr, CQK, 0);

    // 5. softmax rows (rounds output)
    softmax4096<<<BB * NNp, 256>>>(p_e);

    // 6. o[m][co] = attn @ v^T : M=4096, N=256, K=4096
    tc_gemm<<<dim3(CC / 128, NNp / 128, BB), 256, SMEM>>>(
        p_e, NNp, sE,
        p_v, NNp, sX,
        nullptr, 0, 0, NNp,
        p_o, CC, sX,
        nullptr, NNp, 1);

    // 7. y = Wo @ concat(o, x)^T + bo : M=256, N=4096, K=512 (split 256/256)
    tc_gemm<<<dim3(NNp / 128, CC / 128, BB), 256, SMEM>>>(
        p_wo, 2 * CC, 0,
        p_o, CC, sX,
        p_xT, CC, sX, CC,
        y, NNp, sX,
        bo, 2 * CC, 0);
}

// round 7
// speedup vs baseline: 3.3745x; 1.0686x over previous
#include <cuda_runtime.h>
#include <cstdint>
#include <math.h>

// Problem constants
#define BB   4
#define CC   256
#define CQK  32
#define NNp  4096

// ---------------- scratch ----------------
__device__ float  g_q [(size_t)BB * NNp * CQK];   // [b][m][32]  K-major, tf32
__device__ float  g_k [(size_t)BB * NNp * CQK];   // [b][n][32]  K-major, tf32
__device__ float  g_v [(size_t)BB * CC * NNp];    // [b][c][n]   tf32
__device__ float  g_o [(size_t)BB * NNp * CC];    // [b][m][c]   tf32
__device__ float  g_xT[(size_t)BB * NNp * CC];    // [b][m][c]   tf32
__device__ float  g_wv[(size_t)CC * CC];
__device__ float  g_wo[(size_t)CC * 2 * CC];
__device__ float2 g_st[(size_t)BB * NNp];         // per-row (max, 1/sum)

// ---------------- helpers ----------------
__device__ __forceinline__ float tf32r(float x) {
    uint32_t y;
    asm("cvt.rna.tf32.f32 %0, %1;" : "=r"(y) : "f"(x));
    return __uint_as_float(y);
}

__device__ __forceinline__ uint32_t smem_u32(const void* p) {
    uint32_t a;
    asm("{ .reg .u64 t; cvta.to.shared.u64 t, %1; cvt.u32.u64 %0, t; }"
        : "=r"(a) : "l"(p));
    return a;
}

#define CP_ASYNC16(dst, src) \
    asm volatile("cp.async.cg.shared.global [%0], [%1], 16;" :: "r"(dst), "l"(src))
#define CP_COMMIT() asm volatile("cp.async.commit_group;" ::: "memory")
#define CP_WAIT(n)  asm volatile("cp.async.wait_group %0;" :: "n"(n) : "memory")

__device__ __forceinline__ void mma_tf32(float* d, const uint32_t* a, const uint32_t* b) {
    asm volatile(
        "mma.sync.aligned.m16n8k8.row.col.f32.tf32.tf32.f32 "
        "{%0,%1,%2,%3}, {%4,%5,%6,%7}, {%8,%9}, {%0,%1,%2,%3};"
        : "+f"(d[0]), "+f"(d[1]), "+f"(d[2]), "+f"(d[3])
        : "r"(a[0]), "r"(a[1]), "r"(a[2]), "r"(a[3]), "r"(b[0]), "r"(b[1]));
}

// load A-fragment (m16k8) from smem tile with row stride `str`
__device__ __forceinline__ void lda_frag(uint32_t* a, const float* p, int str) {
    a[0] = __float_as_uint(p[0]);
    a[1] = __float_as_uint(p[8 * str]);
    a[2] = __float_as_uint(p[4]);
    a[3] = __float_as_uint(p[8 * str + 4]);
}
__device__ __forceinline__ void ldb_frag(uint32_t* bf, const float* p) {
    bf[0] = __float_as_uint(p[0]);
    bf[1] = __float_as_uint(p[4]);
}

// ---------------- tf32 mma.sync GEMM (unchanged, passing) ----------------
#define SROW 36
#define TILE_F (128 * SROW)

__global__ void __launch_bounds__(256, 2) tc_gemm(
    const float* __restrict__ A, int lda, size_t sAb,
    const float* __restrict__ B1, int ldb1, size_t sB1b,
    const float* __restrict__ B2, int ldb2, size_t sB2b, int ksplit,
    float* __restrict__ C, int ldc, size_t sCb,
    const float* __restrict__ bias, int K, int round_out)
{
    extern __shared__ float4 smem4[];
    float* sm = (float*)smem4;

    const int b = blockIdx.z;
    A  += (size_t)b * sAb;
    B1 += (size_t)b * sB1b;
    const float* B2p = B2 ? (B2 + (size_t)b * sB2b) : nullptr;
    C  += (size_t)b * sCb;

    const int n0 = blockIdx.x * 128;
    const int m0 = blockIdx.y * 128;
    const int t    = threadIdx.x;
    const int lane = t & 31;
    const int warp = t >> 5;
    const int wm = (warp & 3) * 32;
    const int wn = (warp >> 2) * 64;
    const int gr = lane >> 2;
    const int gc = lane & 3;

    const uint32_t sbase = smem_u32(sm);
    const int ldr = t >> 3;
    const int ldc4 = (t & 7) * 4;

    const int nk = K / 32;

    auto issue_tile = [&](int kb, int buf) {
        const int k0 = kb * 32;
        {
            const float* src = A + (size_t)(m0 + ldr) * lda + k0 + ldc4;
            uint32_t dst = sbase + (uint32_t)(buf * 2 * TILE_F) * 4u
                         + (uint32_t)(ldr * SROW + ldc4) * 4u;
#pragma unroll
            for (int i = 0; i < 4; i++)
                CP_ASYNC16(dst + (uint32_t)(i * 32 * SROW) * 4u,
                           src + (size_t)(i * 32) * lda);
        }
        {
            const float* Bp; int ldb, kk;
            if (k0 < ksplit) { Bp = B1;  ldb = ldb1; kk = k0; }
            else             { Bp = B2p; ldb = ldb2; kk = k0 - ksplit; }
            const float* src = Bp + (size_t)(n0 + ldr) * ldb + kk + ldc4;
            uint32_t dst = sbase + (uint32_t)((buf * 2 + 1) * TILE_F) * 4u
                         + (uint32_t)(ldr * SROW + ldc4) * 4u;
#pragma unroll
            for (int i = 0; i < 4; i++)
                CP_ASYNC16(dst + (uint32_t)(i * 32 * SROW) * 4u,
                           src + (size_t)(i * 32) * ldb);
        }
        CP_COMMIT();
    };

    float acc[2][8][4];
#pragma unroll
    for (int mf = 0; mf < 2; mf++)
#pragma unroll
        for (int nf = 0; nf < 8; nf++)
#pragma unroll
            for (int j = 0; j < 4; j++) acc[mf][nf][j] = 0.f;

    issue_tile(0, 0);

    for (int kb = 0; kb < nk; kb++) {
        const int buf = kb & 1;
        if (kb + 1 < nk) { issue_tile(kb + 1, buf ^ 1); CP_WAIT(1); }
        else             { CP_WAIT(0); }
        __syncthreads();

        const float* sA = sm + buf * 2 * TILE_F;
        const float* sB = sA + TILE_F;
#pragma unroll
        for (int ks = 0; ks < 4; ks++) {
            const int k0 = ks * 8;
            uint32_t afr[2][4], bfr[8][2];
#pragma unroll
            for (int mf = 0; mf < 2; mf++)
                lda_frag(afr[mf], sA + (wm + mf * 16 + gr) * SROW + k0 + gc, SROW);
#pragma unroll
            for (int nf = 0; nf < 8; nf++)
                ldb_frag(bfr[nf], sB + (wn + nf * 8 + gr) * SROW + k0 + gc);
#pragma unroll
            for (int mf = 0; mf < 2; mf++)
#pragma unroll
                for (int nf = 0; nf < 8; nf++)
                    mma_tf32(acc[mf][nf], afr[mf], bfr[nf]);
        }
        __syncthreads();
    }

#pragma unroll
    for (int mf = 0; mf < 2; mf++) {
        const int m = m0 + wm + mf * 16 + gr;
        const float bi0 = bias ? bias[m]     : 0.f;
        const float bi1 = bias ? bias[m + 8] : 0.f;
#pragma unroll
        for (int nf = 0; nf < 8; nf++) {
            const int n = n0 + wn + nf * 8 + gc * 2;
            float2 r0, r1;
            r0.x = acc[mf][nf][0] + bi0; r0.y = acc[mf][nf][1] + bi0;
            r1.x = acc[mf][nf][2] + bi1; r1.y = acc[mf][nf][3] + bi1;
            if (round_out) {
                r0.x = tf32r(r0.x); r0.y = tf32r(r0.y);
                r1.x = tf32r(r1.x); r1.y = tf32r(r1.y);
            }
            *(float2*)&C[(size_t)m * ldc + n]       = r0;
            *(float2*)&C[(size_t)(m + 8) * ldc + n] = r1;
        }
    }
}

// ---------------- pass A: per-row softmax stats (max, 1/sum) ----------------
// grid (32, 1, 4), 256 threads (8 warps: 4m x 2n), n-tile 128
__global__ void __launch_bounds__(256) attn_stats(
    const float* __restrict__ q, const float* __restrict__ k,
    float2* __restrict__ stats)
{
    extern __shared__ float sms[];
    float*  sQ   = sms;                 // 128*36
    float*  sK   = sms + 4608;          // 2 x 128*36
    float2* sRed = (float2*)(sms + 13824);  // 128*2

    const int b  = blockIdx.z;
    const int m0 = blockIdx.x * 128;
    const float* qb = q + (size_t)b * NNp * CQK + (size_t)m0 * CQK;
    const float* kb = k + (size_t)b * NNp * CQK;

    const int t = threadIdx.x;
    const int lane = t & 31, warp = t >> 5;
    const int qm = warp & 3, qn = warp >> 2;   // qn 0..1
    const int gr = lane >> 2, gc = lane & 3;

    const uint32_t sQb = smem_u32(sQ);
    const uint32_t sKb = smem_u32(sK);

    // prologue: Q + K(0)
#pragma unroll
    for (int i = 0; i < 4; i++) {
        int idx = t + i * 256;               // 1024 float4
        int r = idx >> 3, c4 = (idx & 7) * 4;
        CP_ASYNC16(sQb + (uint32_t)(r * 36 + c4) * 4u, qb + (size_t)r * CQK + c4);
        CP_ASYNC16(sKb + (uint32_t)(r * 36 + c4) * 4u, kb + (size_t)r * CQK + c4);
    }
    CP_COMMIT(); CP_WAIT(0); __syncthreads();

    float rm[4], rs[4];
#pragma unroll
    for (int i = 0; i < 4; i++) { rm[i] = -3.4e38f; rs[i] = 0.f; }

    for (int it = 0; it < 32; it++) {
        const int buf = it & 1;
        const float* sKbuf = sK + buf * 4608;

        float acc[2][8][4];
#pragma unroll
        for (int mf = 0; mf < 2; mf++)
#pragma unroll
            for (int nf = 0; nf < 8; nf++)
#pragma unroll
                for (int j = 0; j < 4; j++) acc[mf][nf][j] = 0.f;

#pragma unroll
        for (int ks = 0; ks < 4; ks++) {
            uint32_t afr[2][4], bfr[8][2];
#pragma unroll
            for (int mf = 0; mf < 2; mf++)
                lda_frag(afr[mf], sQ + (qm * 32 + mf * 16 + gr) * 36 + ks * 8 + gc, 36);
#pragma unroll
            for (int nf = 0; nf < 8; nf++)
                ldb_frag(bfr[nf], sKbuf + (qn * 64 + nf * 8 + gr) * 36 + ks * 8 + gc);
#pragma unroll
            for (int mf = 0; mf < 2; mf++)
#pragma unroll
                for (int nf = 0; nf < 8; nf++)
                    mma_tf32(acc[mf][nf], afr[mf], bfr[nf]);
        }
        __syncthreads();   // all warps done with sK[buf^1] from prev iter? (done with this buf; safe to refill other)

        if (it + 1 < 32) {
            const float* src = kb + (size_t)(it + 1) * 128 * CQK;
            uint32_t dstb = sKb + (uint32_t)((buf ^ 1) * 4608) * 4u;
#pragma unroll
            for (int i = 0; i < 4; i++) {
                int idx = t + i * 256;
                int r = idx >> 3, c4 = (idx & 7) * 4;
                CP_ASYNC16(dstb + (uint32_t)(r * 36 + c4) * 4u, src + (size_t)r * CQK + c4);
            }
            CP_COMMIT();
        }

        // online (max, sum) update
#pragma unroll
        for (int mf = 0; mf < 2; mf++)
#pragma unroll
            for (int half = 0; half < 2; half++) {
                const int idx = mf * 2 + half;
                float vmax = -3.4e38f;
#pragma unroll
                for (int nf = 0; nf < 8; nf++) {
                    vmax = fmaxf(vmax, acc[mf][nf][half * 2]);
                    vmax = fmaxf(vmax, acc[mf][nf][half * 2 + 1]);
                }
                float mnew = fmaxf(rm[idx], vmax);
                float sadd = 0.f;
#pragma unroll
                for (int nf = 0; nf < 8; nf++) {
                    sadd += __expf(acc[mf][nf][half * 2]     - mnew);
                    sadd += __expf(acc[mf][nf][half * 2 + 1] - mnew);
                }
                rs[idx] = rs[idx] * __expf(rm[idx] - mnew) + sadd;
                rm[idx] = mnew;
            }

        if (it + 1 < 32) { CP_WAIT(0); }
        __syncthreads();
    }

    // reduce across gc lanes
#pragma unroll
    for (int o = 1; o <= 2; o <<= 1)
#pragma unroll
        for (int idx = 0; idx < 4; idx++) {
            float om = __shfl_xor_sync(0xffffffffu, rm[idx], o);
            float os = __shfl_xor_sync(0xffffffffu, rs[idx], o);
            float M = fmaxf(rm[idx], om);
            rs[idx] = rs[idx] * __expf(rm[idx] - M) + os * __expf(om - M);
            rm[idx] = M;
        }
    if (gc == 0) {
#pragma unroll
        for (int mf = 0; mf < 2; mf++)
#pragma unroll
            for (int half = 0; half < 2; half++) {
                int row = qm * 32 + mf * 16 + half * 8 + gr;
                sRed[row * 2 + qn] = make_float2(rm[mf * 2 + half], rs[mf * 2 + half]);
            }
    }
    __syncthreads();
    if (t < 128) {
        float2 a = sRed[t * 2 + 0], c = sRed[t * 2 + 1];
        float M = fmaxf(a.x, c.x);
        float S = a.y * __expf(a.x - M) + c.y * __expf(c.x - M);
        stats[(size_t)b * NNp + m0 + t] = make_float2(M, 1.f / S);
    }
}

// ---------------- pass B: fused QK-softmax-PV ----------------
// grid (32, 1, 4), 512 threads (16 warps). m-tile 128, n-tile 64.
// o[b][m][c] = sum_n exp(S[m][n]-max[m])*invsum[m] * v[c][n], tf32-rounded.
#define OQ 0
#define OK 4608        // 2 x 64*36
#define OP 9216        // 128*68
#define OV 17920       // 2 x 256*68
#define OST 52736      // 128 float2
#define SMB_F 52992

__global__ void __launch_bounds__(512) attn_pv(
    const float* __restrict__ q, const float* __restrict__ k,
    const float* __restrict__ v, const float2* __restrict__ stats,
    float* __restrict__ o)
{
    extern __shared__ float smf[];
    float* sQ = smf + OQ;
    float* sK = smf + OK;
    float* sP = smf + OP;
    float* sV = smf + OV;
    float2* sSt = (float2*)(smf + OST);

    const int b  = blockIdx.z;
    const int m0 = blockIdx.x * 128;
    const float* qb = q + (size_t)b * NNp * CQK + (size_t)m0 * CQK;
    const float* kb = k + (size_t)b * NNp * CQK;
    const float* vb = v + (size_t)b * CC * NNp;

    const int t = threadIdx.x;
    const int lane = t & 31, warp = t >> 5;
    const int wm = warp & 3;      // m sub-tile (QK and PV)
    const int wq = warp >> 5;     (void)wq;
    const int qn = warp >> 2;     // QK: n sub (0..3, 16 wide)
    const int pc = warp >> 2;     // PV: c sub (0..3, 64 wide)
    const int gr = lane >> 2, gc = lane & 3;

    const uint32_t sQb = smem_u32(sQ), sKb = smem_u32(sK), sVb = smem_u32(sV);

    // prologue: Q, K(0), V(0), stats
#pragma unroll
    for (int i = 0; i < 2; i++) {            // Q: 1024 f4
        int idx = t + i * 512;
        int r = idx >> 3, c4 = (idx & 7) * 4;
        CP_ASYNC16(sQb + (uint32_t)(r * 36 + c4) * 4u, qb + (size_t)r * CQK + c4);
    }
    {                                        // K(0): 512 f4
        int r = t >> 3, c4 = (t & 7) * 4;
        CP_ASYNC16(sKb + (uint32_t)(r * 36 + c4) * 4u, kb + (size_t)r * CQK + c4);
    }
#pragma unroll
    for (int i = 0; i < 8; i++) {            // V(0): 4096 f4
        int idx = t + i * 512;
        int r = idx >> 4, c4 = (idx & 15) * 4;
        CP_ASYNC16(sVb + (uint32_t)(r * 68 + c4) * 4u, vb + (size_t)r * NNp + c4);
    }
    if (t < 128) sSt[t] = stats[(size_t)b * NNp + m0 + t];
    CP_COMMIT(); CP_WAIT(0); __syncthreads();

    float O[2][8][4];
#pragma unroll
    for (int mf = 0; mf < 2; mf++)
#pragma unroll
        for (int cf = 0; cf < 8; cf++)
#pragma unroll
            for (int j = 0; j < 4; j++) O[mf][cf][j] = 0.f;

    for (int it = 0; it < 64; it++) {
        const int buf = it & 1;
        const float* sKbuf = sK + buf * (64 * 36);
        const float* sVbuf = sV + buf * (256 * 68);

        // ---- S = Q x K(it)^T : warp 32m x 16n ----
        float sacc[2][2][4];
#pragma unroll
        for (int mf = 0; mf < 2; mf++)
#pragma unroll
            for (int nf = 0; nf < 2; nf++)
#pragma unroll
                for (int j = 0; j < 4; j++) sacc[mf][nf][j] = 0.f;
#pragma unroll
        for (int ks = 0; ks < 4; ks++) {
            uint32_t afr[2][4], bfr[2][2];
#pragma unroll
            for (int mf = 0; mf < 2; mf++)
                lda_frag(afr[mf], sQ + (wm * 32 + mf * 16 + gr) * 36 + ks * 8 + gc, 36);
#pragma unroll
            for (int nf = 0; nf < 2; nf++)
                ldb_frag(bfr[nf], sKbuf + (qn * 16 + nf * 8 + gr) * 36 + ks * 8 + gc);
#pragma unroll
            for (int mf = 0; mf < 2; mf++)
#pragma unroll
                for (int nf = 0; nf < 2; nf++)
                    mma_tf32(sacc[mf][nf], afr[mf], bfr[nf]);
        }
        __syncthreads();   // all warps: done with K(it) reads, done with PV(it-1) (sP, sV[buf^1])

        // prefetch K(it+1), V(it+1) into the ^1 buffers
        if (it + 1 < 64) {
            {
                const float* src = kb + (size_t)(it + 1) * 64 * CQK;
                int r = t >> 3, c4 = (t & 7) * 4;
                CP_ASYNC16(sKb + (uint32_t)((buf ^ 1) * 64 * 36 + r * 36 + c4) * 4u,
                           src + (size_t)r * CQK + c4);
            }
            {
                const float* src = vb + (size_t)(it + 1) * 64;
                uint32_t dstb = sVb + (uint32_t)((buf ^ 1) * 256 * 68) * 4u;
#pragma unroll
                for (int i = 0; i < 8; i++) {
                    int idx = t + i * 512;
                    int r = idx >> 4, c4 = (idx & 15) * 4;
                    CP_ASYNC16(dstb + (uint32_t)(r * 68 + c4) * 4u,
                               src + (size_t)r * NNp + c4);
                }
            }
            CP_COMMIT();
        }

        // ---- softmax apply -> sP (tf32-rounded) ----
#pragma unroll
        for (int mf = 0; mf < 2; mf++)
#pragma unroll
            for (int half = 0; half < 2; half++) {
                const int row = wm * 32 + mf * 16 + half * 8 + gr;
                const float2 st = sSt[row];
#pragma unroll
                for (int nf = 0; nf < 2; nf++) {
                    const int col = qn * 16 + nf * 8 + gc * 2;
                    float p0 = __expf(sacc[mf][nf][half * 2]     - st.x) * st.y;
                    float p1 = __expf(sacc[mf][nf][half * 2 + 1] - st.x) * st.y;
                    *(float2*)&sP[row * 68 + col] = make_float2(tf32r(p0), tf32r(p1));
                }
            }
        __syncthreads();   // sP ready

        // ---- O += P x V(it)^T : warp 32m x 64c ----
#pragma unroll
        for (int ks = 0; ks < 8; ks++) {
            uint32_t afr[2][4], bfr[8][2];
#pragma unroll
            for (int mf = 0; mf < 2; mf++)
                lda_frag(afr[mf], sP + (wm * 32 + mf * 16 + gr) * 68 + ks * 8 + gc, 68);
#pragma unroll
            for (int cf = 0; cf < 8; cf++)
                ldb_frag(bfr[cf], sVbuf + (pc * 64 + cf * 8 + gr) * 68 + ks * 8 + gc);
#pragma unroll
            for (int mf = 0; mf < 2; mf++)
#pragma unroll
                for (int cf = 0; cf < 8; cf++)
                    mma_tf32(O[mf][cf], afr[mf], bfr[cf]);
        }

        if (it + 1 < 64) { CP_WAIT(0); }
        __syncthreads();   // loads visible to all before next S
    }

    // ---- epilogue: write O (tf32-rounded) ----
    float* ob = o + (size_t)b * NNp * CC + (size_t)m0 * CC;
#pragma unroll
    for (int mf = 0; mf < 2; mf++) {
        const int r = wm * 32 + mf * 16 + gr;
#pragma unroll
        for (int cf = 0; cf < 8; cf++) {
            const int c = pc * 64 + cf * 8 + gc * 2;
            *(float2*)&ob[(size_t)r * CC + c] =
                make_float2(tf32r(O[mf][cf][0]), tf32r(O[mf][cf][1]));
            *(float2*)&ob[(size_t)(r + 8) * CC + c] =
                make_float2(tf32r(O[mf][cf][2]), tf32r(O[mf][cf][3]));
        }
    }
}

// ---------------- weight rounding prep ----------------
__global__ void round_weights(const float* __restrict__ Wv, const float* __restrict__ Wo,
                              float* __restrict__ wv_r, float* __restrict__ wo_r)
{
    int i = blockIdx.x * 256 + threadIdx.x;
    if (i < CC * CC)     wv_r[i] = tf32r(Wv[i]);
    if (i < CC * 2 * CC) wo_r[i] = tf32r(Wo[i]);
}

// ---------------- fused q/k projection (unchanged) ----------------
__global__ void qk_proj_kernel(const float* __restrict__ x,
                               const float* __restrict__ Wq, const float* __restrict__ bq,
                               const float* __restrict__ Wk, const float* __restrict__ bk,
                               float* __restrict__ q, float* __restrict__ ko)
{
    const int b  = blockIdx.z;
    const int m0 = blockIdx.x * 128;
    const float* xb = x + (size_t)b * CC * NNp;

    __shared__ float sx[32][128];
    __shared__ float sw[64][32];

    const int t    = threadIdx.x;
    const int mi   = t & 127;
    const int half = t >> 7;

    float acc[32];
    const float* bias = half ? bk : bq;
#pragma unroll
    for (int j = 0; j < 32; j++) acc[j] = bias[j];

    for (int c0 = 0; c0 < CC; c0 += 32) {
#pragma unroll
        for (int i = 0; i < 16; i++) {
            int idx = t + i * 256;
            int r = idx >> 7, mm = idx & 127;
            sx[r][mm] = xb[(size_t)(c0 + r) * NNp + m0 + mm];
        }
#pragma unroll
        for (int i = 0; i < 8; i++) {
            int idx = t + i * 256;
            int co = idx >> 5, cc = idx & 31;
            sw[co][cc] = (co < 32) ? Wq[co * 256 + c0 + cc]
                                   : Wk[(co - 32) * 256 + c0 + cc];
        }
        __syncthreads();
#pragma unroll
        for (int cc = 0; cc < 32; cc++) {
            float xv = sx[cc][mi];
#pragma unroll
            for (int j = 0; j < 32; j++) acc[j] += sw[half * 32 + j][cc] * xv;
        }
        __syncthreads();
    }

    float* dst = (half ? ko : q) + (size_t)b * NNp * CQK + (size_t)(m0 + mi) * CQK;
#pragma unroll
    for (int j = 0; j < 32; j += 4)
        *(float4*)&dst[j] = make_float4(tf32r(acc[j]), tf32r(acc[j + 1]),
                                        tf32r(acc[j + 2]), tf32r(acc[j + 3]));
}

// ---------------- 32x32 transpose with tf32 rounding ----------------
__global__ void transpose_kernel(const float* __restrict__ src, float* __restrict__ dst,
                                 int R, int Cn, size_t sSb, size_t sDb)
{
    __shared__ float tile[32][33];
    const int b = blockIdx.z;
    src += (size_t)b * sSb;
    dst += (size_t)b * sDb;
    const int c0 = blockIdx.x * 32;
    const int r0 = blockIdx.y * 32;
    const int tx = threadIdx.x, ty = threadIdx.y;
#pragma unroll
    for (int i = 0; i < 32; i += 8)
        tile[ty + i][tx] = tf32r(src[(size_t)(r0 + ty + i) * Cn + c0 + tx]);
    __syncthreads();
#pragma unroll
    for (int i = 0; i < 32; i += 8)
        dst[(size_t)(c0 + ty + i) * R + r0 + tx] = tile[tx][ty + i];
}

// ---------------- launch ----------------
extern "C" void kernel_launch(void* const* d_in, const int* in_sizes, int n_in,
                              void* d_out, int out_size)
{
    const float* x  = (const float*)d_in[0];
    const float* Wq = (const float*)d_in[1];
    const float* bq = (const float*)d_in[2];
    const float* Wk = (const float*)d_in[3];
    const float* bk = (const float*)d_in[4];
    const float* Wv = (const float*)d_in[5];
    const float* bv = (const float*)d_in[6];
    const float* Wo = (const float*)d_in[7];
    const float* bo = (const float*)d_in[8];
    float* y = (float*)d_out;

    float *p_q, *p_k, *p_v, *p_o, *p_xT, *p_wv, *p_wo;
    float2* p_st;
    cudaGetSymbolAddress((void**)&p_q,  g_q);
    cudaGetSymbolAddress((void**)&p_k,  g_k);
    cudaGetSymbolAddress((void**)&p_v,  g_v);
    cudaGetSymbolAddress((void**)&p_o,  g_o);
    cudaGetSymbolAddress((void**)&p_xT, g_xT);
    cudaGetSymbolAddress((void**)&p_wv, g_wv);
    cudaGetSymbolAddress((void**)&p_wo, g_wo);
    cudaGetSymbolAddress((void**)&p_st, g_st);

    const size_t sX = (size_t)CC * NNp;

    const int SMEM_G = 4 * TILE_F * 4;
    cudaFuncSetAttribute(tc_gemm, cudaFuncAttributeMaxDynamicSharedMemorySize, SMEM_G);
    const int SMEM_A = 14336 * 4;
    cudaFuncSetAttribute(attn_stats, cudaFuncAttributeMaxDynamicSharedMemorySize, SMEM_A);
    const int SMEM_B = SMB_F * 4;
    cudaFuncSetAttribute(attn_pv, cudaFuncAttributeMaxDynamicSharedMemorySize, SMEM_B);

    round_weights<<<(CC * 2 * CC + 255) / 256, 256>>>(Wv, Wo, p_wv, p_wo);

    transpose_kernel<<<dim3(NNp / 32, CC / 32, BB), dim3(32, 8)>>>(
        x, p_xT, CC, NNp, sX, sX);

    qk_proj_kernel<<<dim3(NNp / 128, 1, BB), 256>>>(x, Wq, bq, Wk, bk, p_q, p_k);

    // v[c][n] = Wv @ x + bv
    tc_gemm<<<dim3(NNp / 128, CC / 128, BB), 256, SMEM_G>>>(
        p_wv, CC, 0,
        p_xT, CC, sX,
        nullptr, 0, 0, CC,
        p_v, NNp, sX,
        bv, CC, 1);

    // pass A: row stats
    attn_stats<<<dim3(NNp / 128, 1, BB), 256, SMEM_A>>>(p_q, p_k, p_st);

    // pass B: fused attention -> g_o [m][c]
    attn_pv<<<dim3(NNp / 128, 1, BB), 512, SMEM_B>>>(p_q, p_k, p_v, p_st, p_o);

    // y = Wo @ concat(o, x)^T + bo
    tc_gemm<<<dim3(NNp / 128, CC / 128, BB), 256, SMEM_G>>>(
        p_wo, 2 * CC, 0,
        p_o, CC, sX,
        p_xT, CC, sX, CC,
        y, NNp, sX,
        bo, 2 * CC, 0);
}

// round 8
// speedup vs baseline: 3.9967x; 1.1844x over previous
#include <cuda_runtime.h>
#include <cstdint>
#include <math.h>

// Problem constants
#define BB   4
#define CC   256
#define CQK  32
#define NNp  4096

// ---------------- scratch ----------------
__device__ float  g_q [(size_t)BB * NNp * CQK];   // [b][m][32]  K-major, tf32, pre-scaled by log2e
__device__ float  g_k [(size_t)BB * NNp * CQK];   // [b][n][32]  K-major, tf32
__device__ float  g_v [(size_t)BB * CC * NNp];    // [b][c][n]   tf32
__device__ float  g_o [(size_t)BB * NNp * CC];    // [b][m][c]   tf32
__device__ float  g_xT[(size_t)BB * NNp * CC];    // [b][m][c]   tf32
__device__ float  g_wv[(size_t)CC * CC];
__device__ float  g_wo[(size_t)CC * 2 * CC];

// ---------------- helpers ----------------
__device__ __forceinline__ float tf32r(float x) {
    uint32_t y;
    asm("cvt.rna.tf32.f32 %0, %1;" : "=r"(y) : "f"(x));
    return __uint_as_float(y);
}

__device__ __forceinline__ float ex2f(float x) {
    float y;
    asm("ex2.approx.f32 %0, %1;" : "=f"(y) : "f"(x));
    return y;
}

__device__ __forceinline__ uint32_t smem_u32(const void* p) {
    uint32_t a;
    asm("{ .reg .u64 t; cvta.to.shared.u64 t, %1; cvt.u32.u64 %0, t; }"
        : "=r"(a) : "l"(p));
    return a;
}

#define CP_ASYNC16(dst, src) \
    asm volatile("cp.async.cg.shared.global [%0], [%1], 16;" :: "r"(dst), "l"(src))
#define CP_COMMIT() asm volatile("cp.async.commit_group;" ::: "memory")
#define CP_WAIT(n)  asm volatile("cp.async.wait_group %0;" :: "n"(n) : "memory")

__device__ __forceinline__ void mma_tf32(float* d, const uint32_t* a, const uint32_t* b) {
    asm volatile(
        "mma.sync.aligned.m16n8k8.row.col.f32.tf32.tf32.f32 "
        "{%0,%1,%2,%3}, {%4,%5,%6,%7}, {%8,%9}, {%0,%1,%2,%3};"
        : "+f"(d[0]), "+f"(d[1]), "+f"(d[2]), "+f"(d[3])
        : "r"(a[0]), "r"(a[1]), "r"(a[2]), "r"(a[3]), "r"(b[0]), "r"(b[1]));
}

__device__ __forceinline__ void lda_frag(uint32_t* a, const float* p, int str) {
    a[0] = __float_as_uint(p[0]);
    a[1] = __float_as_uint(p[8 * str]);
    a[2] = __float_as_uint(p[4]);
    a[3] = __float_as_uint(p[8 * str + 4]);
}
__device__ __forceinline__ void ldb_frag(uint32_t* bf, const float* p) {
    bf[0] = __float_as_uint(p[0]);
    bf[1] = __float_as_uint(p[4]);
}

// ---------------- tf32 mma.sync GEMM (unchanged, proven) ----------------
#define SROW 36
#define TILE_F (128 * SROW)

__global__ void __launch_bounds__(256, 2) tc_gemm(
    const float* __restrict__ A, int lda, size_t sAb,
    const float* __restrict__ B1, int ldb1, size_t sB1b,
    const float* __restrict__ B2, int ldb2, size_t sB2b, int ksplit,
    float* __restrict__ C, int ldc, size_t sCb,
    const float* __restrict__ bias, int K, int round_out)
{
    extern __shared__ float4 smem4[];
    float* sm = (float*)smem4;

    const int b = blockIdx.z;
    A  += (size_t)b * sAb;
    B1 += (size_t)b * sB1b;
    const float* B2p = B2 ? (B2 + (size_t)b * sB2b) : nullptr;
    C  += (size_t)b * sCb;

    const int n0 = blockIdx.x * 128;
    const int m0 = blockIdx.y * 128;
    const int t    = threadIdx.x;
    const int lane = t & 31;
    const int warp = t >> 5;
    const int wm = (warp & 3) * 32;
    const int wn = (warp >> 2) * 64;
    const int gr = lane >> 2;
    const int gc = lane & 3;

    const uint32_t sbase = smem_u32(sm);
    const int ldr = t >> 3;
    const int ldc4 = (t & 7) * 4;

    const int nk = K / 32;

    auto issue_tile = [&](int kb, int buf) {
        const int k0 = kb * 32;
        {
            const float* src = A + (size_t)(m0 + ldr) * lda + k0 + ldc4;
            uint32_t dst = sbase + (uint32_t)(buf * 2 * TILE_F) * 4u
                         + (uint32_t)(ldr * SROW + ldc4) * 4u;
#pragma unroll
            for (int i = 0; i < 4; i++)
                CP_ASYNC16(dst + (uint32_t)(i * 32 * SROW) * 4u,
                           src + (size_t)(i * 32) * lda);
        }
        {
            const float* Bp; int ldb, kk;
            if (k0 < ksplit) { Bp = B1;  ldb = ldb1; kk = k0; }
            else             { Bp = B2p; ldb = ldb2; kk = k0 - ksplit; }
            const float* src = Bp + (size_t)(n0 + ldr) * ldb + kk + ldc4;
            uint32_t dst = sbase + (uint32_t)((buf * 2 + 1) * TILE_F) * 4u
                         + (uint32_t)(ldr * SROW + ldc4) * 4u;
#pragma unroll
            for (int i = 0; i < 4; i++)
                CP_ASYNC16(dst + (uint32_t)(i * 32 * SROW) * 4u,
                           src + (size_t)(i * 32) * ldb);
        }
        CP_COMMIT();
    };

    float acc[2][8][4];
#pragma unroll
    for (int mf = 0; mf < 2; mf++)
#pragma unroll
        for (int nf = 0; nf < 8; nf++)
#pragma unroll
            for (int j = 0; j < 4; j++) acc[mf][nf][j] = 0.f;

    issue_tile(0, 0);

    for (int kb = 0; kb < nk; kb++) {
        const int buf = kb & 1;
        if (kb + 1 < nk) { issue_tile(kb + 1, buf ^ 1); CP_WAIT(1); }
        else             { CP_WAIT(0); }
        __syncthreads();

        const float* sA = sm + buf * 2 * TILE_F;
        const float* sB = sA + TILE_F;
#pragma unroll
        for (int ks = 0; ks < 4; ks++) {
            const int k0 = ks * 8;
            uint32_t afr[2][4], bfr[8][2];
#pragma unroll
            for (int mf = 0; mf < 2; mf++)
                lda_frag(afr[mf], sA + (wm + mf * 16 + gr) * SROW + k0 + gc, SROW);
#pragma unroll
            for (int nf = 0; nf < 8; nf++)
                ldb_frag(bfr[nf], sB + (wn + nf * 8 + gr) * SROW + k0 + gc);
#pragma unroll
            for (int mf = 0; mf < 2; mf++)
#pragma unroll
                for (int nf = 0; nf < 8; nf++)
                    mma_tf32(acc[mf][nf], afr[mf], bfr[nf]);
        }
        __syncthreads();
    }

#pragma unroll
    for (int mf = 0; mf < 2; mf++) {
        const int m = m0 + wm + mf * 16 + gr;
        const float bi0 = bias ? bias[m]     : 0.f;
        const float bi1 = bias ? bias[m + 8] : 0.f;
#pragma unroll
        for (int nf = 0; nf < 8; nf++) {
            const int n = n0 + wn + nf * 8 + gc * 2;
            float2 r0, r1;
            r0.x = acc[mf][nf][0] + bi0; r0.y = acc[mf][nf][1] + bi0;
            r1.x = acc[mf][nf][2] + bi1; r1.y = acc[mf][nf][3] + bi1;
            if (round_out) {
                r0.x = tf32r(r0.x); r0.y = tf32r(r0.y);
                r1.x = tf32r(r1.x); r1.y = tf32r(r1.y);
            }
            *(float2*)&C[(size_t)m * ldc + n]       = r0;
            *(float2*)&C[(size_t)(m + 8) * ldc + n] = r1;
        }
    }
}

// ---------------- single-pass fused attention (no-max softmax) ----------------
// grid (32, 1, 4), 512 threads (16 warps: 4 wm x 4 qn/pc). m-tile 128, n-tile 64.
// q pre-scaled by log2(e): P = 2^(q.k), O = (sum_n P*v) / (sum_n P).
#define OQ 0
#define OK 4608        // 2 x 64*36
#define OP 9216        // 128*68
#define OV 17920       // 2 x 256*68
#define OSUM 52736     // 128 x 4 floats
#define SMB_F 53248

__global__ void __launch_bounds__(512) attn_pv(
    const float* __restrict__ q, const float* __restrict__ k,
    const float* __restrict__ v, float* __restrict__ o)
{
    extern __shared__ float smf[];
    float* sQ = smf + OQ;
    float* sK = smf + OK;
    float* sP = smf + OP;
    float* sV = smf + OV;
    float* sSum = smf + OSUM;

    const int b  = blockIdx.z;
    const int m0 = blockIdx.x * 128;
    const float* qb = q + (size_t)b * NNp * CQK + (size_t)m0 * CQK;
    const float* kb = k + (size_t)b * NNp * CQK;
    const float* vb = v + (size_t)b * CC * NNp;

    const int t = threadIdx.x;
    const int lane = t & 31, warp = t >> 5;
    const int wm = warp & 3;      // m sub-tile
    const int qn = warp >> 2;     // QK: 16-wide n quadrant / PV: 64-wide c quadrant
    const int gr = lane >> 2, gc = lane & 3;

    const uint32_t sQb = smem_u32(sQ), sKb = smem_u32(sK), sVb = smem_u32(sV);

    // prologue: Q, K(0), V(0)
#pragma unroll
    for (int i = 0; i < 2; i++) {
        int idx = t + i * 512;
        int r = idx >> 3, c4 = (idx & 7) * 4;
        CP_ASYNC16(sQb + (uint32_t)(r * 36 + c4) * 4u, qb + (size_t)r * CQK + c4);
    }
    {
        int r = t >> 3, c4 = (t & 7) * 4;
        CP_ASYNC16(sKb + (uint32_t)(r * 36 + c4) * 4u, kb + (size_t)r * CQK + c4);
    }
#pragma unroll
    for (int i = 0; i < 8; i++) {
        int idx = t + i * 512;
        int r = idx >> 4, c4 = (idx & 15) * 4;
        CP_ASYNC16(sVb + (uint32_t)(r * 68 + c4) * 4u, vb + (size_t)r * NNp + c4);
    }
    CP_COMMIT(); CP_WAIT(0); __syncthreads();

    float O[2][8][4];
#pragma unroll
    for (int mf = 0; mf < 2; mf++)
#pragma unroll
        for (int cf = 0; cf < 8; cf++)
#pragma unroll
            for (int j = 0; j < 4; j++) O[mf][cf][j] = 0.f;

    float rsum[2][2] = {{0.f, 0.f}, {0.f, 0.f}};

    for (int it = 0; it < 64; it++) {
        const int buf = it & 1;
        const float* sKbuf = sK + buf * (64 * 36);
        const float* sVbuf = sV + buf * (256 * 68);

        // ---- prefetch K(it+1), V(it+1) into ^1 buffers (overlaps whole body) ----
        if (it + 1 < 64) {
            {
                const float* src = kb + (size_t)(it + 1) * 64 * CQK;
                int r = t >> 3, c4 = (t & 7) * 4;
                CP_ASYNC16(sKb + (uint32_t)((buf ^ 1) * 64 * 36 + r * 36 + c4) * 4u,
                           src + (size_t)r * CQK + c4);
            }
            {
                const float* src = vb + (size_t)(it + 1) * 64;
                uint32_t dstb = sVb + (uint32_t)((buf ^ 1) * 256 * 68) * 4u;
#pragma unroll
                for (int i = 0; i < 8; i++) {
                    int idx = t + i * 512;
                    int r = idx >> 4, c4 = (idx & 15) * 4;
                    CP_ASYNC16(dstb + (uint32_t)(r * 68 + c4) * 4u,
                               src + (size_t)r * NNp + c4);
                }
            }
            CP_COMMIT();
        }

        // ---- S = Q x K(it)^T : warp 32m x 16n ----
        float sacc[2][2][4];
#pragma unroll
        for (int mf = 0; mf < 2; mf++)
#pragma unroll
            for (int nf = 0; nf < 2; nf++)
#pragma unroll
                for (int j = 0; j < 4; j++) sacc[mf][nf][j] = 0.f;
#pragma unroll
        for (int ks = 0; ks < 4; ks++) {
            uint32_t afr[2][4], bfr[2][2];
#pragma unroll
            for (int mf = 0; mf < 2; mf++)
                lda_frag(afr[mf], sQ + (wm * 32 + mf * 16 + gr) * 36 + ks * 8 + gc, 36);
#pragma unroll
            for (int nf = 0; nf < 2; nf++)
                ldb_frag(bfr[nf], sKbuf + (qn * 16 + nf * 8 + gr) * 36 + ks * 8 + gc);
#pragma unroll
            for (int mf = 0; mf < 2; mf++)
#pragma unroll
                for (int nf = 0; nf < 2; nf++)
                    mma_tf32(sacc[mf][nf], afr[mf], bfr[nf]);
        }

        // ---- P = 2^S (unnormalized), accumulate row sums, stage to sP ----
        // (prev iteration's PV reads of sP finished before its trailing sync)
#pragma unroll
        for (int mf = 0; mf < 2; mf++)
#pragma unroll
            for (int half = 0; half < 2; half++) {
                const int row = wm * 32 + mf * 16 + half * 8 + gr;
                float part = 0.f;
#pragma unroll
                for (int nf = 0; nf < 2; nf++) {
                    const int col = qn * 16 + nf * 8 + gc * 2;
                    float p0 = tf32r(ex2f(sacc[mf][nf][half * 2]));
                    float p1 = tf32r(ex2f(sacc[mf][nf][half * 2 + 1]));
                    part += p0 + p1;
                    *(float2*)&sP[row * 68 + col] = make_float2(p0, p1);
                }
                rsum[mf][half] += part;
            }
        __syncthreads();   // sP ready for all warps

        // ---- O += P x V(it)^T : warp 32m x 64c ----
#pragma unroll
        for (int ks = 0; ks < 8; ks++) {
            uint32_t afr[2][4], bfr[8][2];
#pragma unroll
            for (int mf = 0; mf < 2; mf++)
                lda_frag(afr[mf], sP + (wm * 32 + mf * 16 + gr) * 68 + ks * 8 + gc, 68);
#pragma unroll
            for (int cf = 0; cf < 8; cf++)
                ldb_frag(bfr[cf], sVbuf + (qn * 64 + cf * 8 + gr) * 68 + ks * 8 + gc);
#pragma unroll
            for (int mf = 0; mf < 2; mf++)
#pragma unroll
                for (int cf = 0; cf < 8; cf++)
                    mma_tf32(O[mf][cf], afr[mf], bfr[cf]);
        }

        if (it + 1 < 64) { CP_WAIT(0); }
        __syncthreads();   // PV reads done; prefetched K/V visible for next iter
    }

    // ---- row-sum reduction across quadrants ----
#pragma unroll
    for (int mf = 0; mf < 2; mf++)
#pragma unroll
        for (int half = 0; half < 2; half++) {
            float r = rsum[mf][half];
            r += __shfl_xor_sync(0xffffffffu, r, 1);
            r += __shfl_xor_sync(0xffffffffu, r, 2);
            if (gc == 0)
                sSum[(wm * 32 + mf * 16 + half * 8 + gr) * 4 + qn] = r;
        }
    __syncthreads();

    // ---- epilogue: normalize + write O (tf32-rounded) ----
    float* ob = o + (size_t)b * NNp * CC + (size_t)m0 * CC;
#pragma unroll
    for (int mf = 0; mf < 2; mf++) {
        const int r0 = wm * 32 + mf * 16 + gr;
        const int r1 = r0 + 8;
        const float inv0 = 1.f / (sSum[r0 * 4] + sSum[r0 * 4 + 1] +
                                  sSum[r0 * 4 + 2] + sSum[r0 * 4 + 3]);
        const float inv1 = 1.f / (sSum[r1 * 4] + sSum[r1 * 4 + 1] +
                                  sSum[r1 * 4 + 2] + sSum[r1 * 4 + 3]);
#pragma unroll
        for (int cf = 0; cf < 8; cf++) {
            const int c = qn * 64 + cf * 8 + gc * 2;
            *(float2*)&ob[(size_t)r0 * CC + c] =
                make_float2(tf32r(O[mf][cf][0] * inv0), tf32r(O[mf][cf][1] * inv0));
            *(float2*)&ob[(size_t)r1 * CC + c] =
                make_float2(tf32r(O[mf][cf][2] * inv1), tf32r(O[mf][cf][3] * inv1));
        }
    }
}

// ---------------- weight rounding prep ----------------
__global__ void round_weights(const float* __restrict__ Wv, const float* __restrict__ Wo,
                              float* __restrict__ wv_r, float* __restrict__ wo_r)
{
    int i = blockIdx.x * 256 + threadIdx.x;
    if (i < CC * CC)     wv_r[i] = tf32r(Wv[i]);
    if (i < CC * 2 * CC) wo_r[i] = tf32r(Wo[i]);
}

// ---------------- fused q/k projection (q scaled by log2e) ----------------
__global__ void qk_proj_kernel(const float* __restrict__ x,
                               const float* __restrict__ Wq, const float* __restrict__ bq,
                               const float* __restrict__ Wk, const float* __restrict__ bk,
                               float* __restrict__ q, float* __restrict__ ko)
{
    const int b  = blockIdx.z;
    const int m0 = blockIdx.x * 128;
    const float* xb = x + (size_t)b * CC * NNp;

    __shared__ float sx[32][128];
    __shared__ float sw[64][32];

    const int t    = threadIdx.x;
    const int mi   = t & 127;
    const int half = t >> 7;

    float acc[32];
    const float* bias = half ? bk : bq;
#pragma unroll
    for (int j = 0; j < 32; j++) acc[j] = bias[j];

    for (int c0 = 0; c0 < CC; c0 += 32) {
#pragma unroll
        for (int i = 0; i < 16; i++) {
            int idx = t + i * 256;
            int r = idx >> 7, mm = idx & 127;
            sx[r][mm] = xb[(size_t)(c0 + r) * NNp + m0 + mm];
        }
#pragma unroll
        for (int i = 0; i < 8; i++) {
            int idx = t + i * 256;
            int co = idx >> 5, cc = idx & 31;
            sw[co][cc] = (co < 32) ? Wq[co * 256 + c0 + cc]
                                   : Wk[(co - 32) * 256 + c0 + cc];
        }
        __syncthreads();
#pragma unroll
        for (int cc = 0; cc < 32; cc++) {
            float xv = sx[cc][mi];
#pragma unroll
            for (int j = 0; j < 32; j++) acc[j] += sw[half * 32 + j][cc] * xv;
        }
        __syncthreads();
    }

    const float scl = half ? 1.f : 1.4426950408889634f;   // log2(e) folded into q
    float* dst = (half ? ko : q) + (size_t)b * NNp * CQK + (size_t)(m0 + mi) * CQK;
#pragma unroll
    for (int j = 0; j < 32; j += 4)
        *(float4*)&dst[j] = make_float4(tf32r(acc[j] * scl), tf32r(acc[j + 1] * scl),
                                        tf32r(acc[j + 2] * scl), tf32r(acc[j + 3] * scl));
}

// ---------------- 32x32 transpose with tf32 rounding ----------------
__global__ void transpose_kernel(const float* __restrict__ src, float* __restrict__ dst,
                                 int R, int Cn, size_t sSb, size_t sDb)
{
    __shared__ float tile[32][33];
    const int b = blockIdx.z;
    src += (size_t)b * sSb;
    dst += (size_t)b * sDb;
    const int c0 = blockIdx.x * 32;
    const int r0 = blockIdx.y * 32;
    const int tx = threadIdx.x, ty = threadIdx.y;
#pragma unroll
    for (int i = 0; i < 32; i += 8)
        tile[ty + i][tx] = tf32r(src[(size_t)(r0 + ty + i) * Cn + c0 + tx]);
    __syncthreads();
#pragma unroll
    for (int i = 0; i < 32; i += 8)
        dst[(size_t)(c0 + ty + i) * R + r0 + tx] = tile[tx][ty + i];
}

// ---------------- launch ----------------
extern "C" void kernel_launch(void* const* d_in, const int* in_sizes, int n_in,
                              void* d_out, int out_size)
{
    const float* x  = (const float*)d_in[0];
    const float* Wq = (const float*)d_in[1];
    const float* bq = (const float*)d_in[2];
    const float* Wk = (const float*)d_in[3];
    const float* bk = (const float*)d_in[4];
    const float* Wv = (const float*)d_in[5];
    const float* bv = (const float*)d_in[6];
    const float* Wo = (const float*)d_in[7];
    const float* bo = (const float*)d_in[8];
    float* y = (float*)d_out;

    float *p_q, *p_k, *p_v, *p_o, *p_xT, *p_wv, *p_wo;
    cudaGetSymbolAddress((void**)&p_q,  g_q);
    cudaGetSymbolAddress((void**)&p_k,  g_k);
    cudaGetSymbolAddress((void**)&p_v,  g_v);
    cudaGetSymbolAddress((void**)&p_o,  g_o);
    cudaGetSymbolAddress((void**)&p_xT, g_xT);
    cudaGetSymbolAddress((void**)&p_wv, g_wv);
    cudaGetSymbolAddress((void**)&p_wo, g_wo);

    const size_t sX = (size_t)CC * NNp;

    const int SMEM_G = 4 * TILE_F * 4;
    cudaFuncSetAttribute(tc_gemm, cudaFuncAttributeMaxDynamicSharedMemorySize, SMEM_G);
    const int SMEM_B = SMB_F * 4;
    cudaFuncSetAttribute(attn_pv, cudaFuncAttributeMaxDynamicSharedMemorySize, SMEM_B);

    round_weights<<<(CC * 2 * CC + 255) / 256, 256>>>(Wv, Wo, p_wv, p_wo);

    transpose_kernel<<<dim3(NNp / 32, CC / 32, BB), dim3(32, 8)>>>(
        x, p_xT, CC, NNp, sX, sX);

    qk_proj_kernel<<<dim3(NNp / 128, 1, BB), 256>>>(x, Wq, bq, Wk, bk, p_q, p_k);

    // v[c][n] = Wv @ x + bv
    tc_gemm<<<dim3(NNp / 128, CC / 128, BB), 256, SMEM_G>>>(
        p_wv, CC, 0,
        p_xT, CC, sX,
        nullptr, 0, 0, CC,
        p_v, NNp, sX,
        bv, CC, 1);

    // single-pass fused attention -> g_o [m][c]
    attn_pv<<<dim3(NNp / 128, 1, BB), 512, SMEM_B>>>(p_q, p_k, p_v, p_o);

    // y = Wo @ concat(o, x)^T + bo
    tc_gemm<<<dim3(NNp / 128, CC / 128, BB), 256, SMEM_G>>>(
        p_wo, 2 * CC, 0,
        p_o, CC, sX,
        p_xT, CC, sX, CC,
        y, NNp, sX,
        bo, 2 * CC, 0);
}